// round 1
// baseline (speedup 1.0000x reference)
#include <cuda_runtime.h>
#include <math.h>

#define NODES 100000

// ---------------- scratch (device globals; no allocation) ----------------
__device__ float g_h0[NODES * 64];     // x @ W0
__device__ float g_skip0[NODES * 64];  // x @ sW0
__device__ float g_ssrc0[NODES];
__device__ float g_sdst0[NODES];
__device__ float g_acc0[NODES * 64];
__device__ float g_denom0[NODES];
__device__ float g_h1[NODES * 64];     // layer-1 input (post ELU)
__device__ float g_h1p[NODES * 32];    // h1 @ W1
__device__ float g_skip1[NODES * 32];  // h1 @ sW1
__device__ float g_ssrc1[NODES];
__device__ float g_sdst1[NODES];
__device__ float g_acc1[NODES * 32];
__device__ float g_denom1[NODES];

// ---------------- helpers ----------------
__device__ __forceinline__ void red_add4(float* p, float4 v) {
    asm volatile("red.global.add.v4.f32 [%0], {%1, %2, %3, %4};"
                 :: "l"(p), "f"(v.x), "f"(v.y), "f"(v.z), "f"(v.w) : "memory");
}

__device__ __forceinline__ float leaky(float x) { return x > 0.f ? x : 0.2f * x; }

// ---------------- dual GEMM: O_a = X@Wa, O_b = X@Wb (both K x CT/2) -------
template<int K, int CT>
__global__ __launch_bounds__(256)
void gemm_dual(const float* __restrict__ X,
               const float* __restrict__ Wa,
               const float* __restrict__ Wb,
               float* __restrict__ Oa,
               float* __restrict__ Ob,
               int n) {
    constexpr int TR   = 32;        // tile rows
    constexpr int PAD  = TR + 4;    // 36 floats: 16B-aligned row stride
    constexpr int NCG  = CT / 4;    // col groups (4 cols each)
    constexpr int NRG  = 256 / NCG; // row groups
    constexpr int R    = TR / NRG;  // rows per thread
    constexpr int HALF = CT / 2;

    __shared__ float xs[K * PAD];

    const int t    = threadIdx.x;
    const int base = blockIdx.x * TR;

    // load X tile transposed: xs[k][r]
    for (int i = t; i < TR * K; i += 256) {
        int r = i / K, k = i - r * K;
        xs[k * PAD + r] = X[(base + r) * K + k];
    }
    __syncthreads();

    const int  cg     = t % NCG;
    const int  rg     = t / NCG;
    const bool second = (cg >= NCG / 2);
    const float* Wsel = second ? Wb : Wa;
    const int  ccol   = (second ? (cg - NCG / 2) : cg) * 4;

    float acc[R][4];
#pragma unroll
    for (int j = 0; j < R; j++)
#pragma unroll
        for (int m = 0; m < 4; m++) acc[j][m] = 0.f;

    const float4* wp = reinterpret_cast<const float4*>(Wsel + ccol);

#pragma unroll 4
    for (int k = 0; k < K; k++) {
        float4 w = wp[k * (HALF / 4)];
        float  xr[R];
        if constexpr (R == 4) {
            float4 v = *reinterpret_cast<const float4*>(&xs[k * PAD + rg * 4]);
            xr[0] = v.x; xr[1] = v.y; xr[2] = v.z; xr[3] = v.w;
        } else {
            float2 v = *reinterpret_cast<const float2*>(&xs[k * PAD + rg * 2]);
            xr[0] = v.x; xr[1] = v.y;
        }
#pragma unroll
        for (int j = 0; j < R; j++) {
            acc[j][0] = fmaf(xr[j], w.x, acc[j][0]);
            acc[j][1] = fmaf(xr[j], w.y, acc[j][1]);
            acc[j][2] = fmaf(xr[j], w.z, acc[j][2]);
            acc[j][3] = fmaf(xr[j], w.w, acc[j][3]);
        }
    }

    float* O = second ? Ob : Oa;
#pragma unroll
    for (int j = 0; j < R; j++) {
        int row = base + rg * R + j;
        if (row < n) {
            float4 v = make_float4(acc[j][0], acc[j][1], acc[j][2], acc[j][3]);
            *reinterpret_cast<float4*>(&O[row * HALF + ccol]) = v;
        }
    }
}

// ---------------- layer 0: per-node init (warp per node, C=64) -----------
__global__ void init0_kernel(const float* __restrict__ asrc,
                             const float* __restrict__ adst, int n) {
    int gw   = (blockIdx.x * blockDim.x + threadIdx.x) >> 5;
    int lane = threadIdx.x & 31;
    if (gw >= n) return;
    float2 hv = reinterpret_cast<const float2*>(g_h0)[gw * 32 + lane];
    float2 as = reinterpret_cast<const float2*>(asrc)[lane];
    float2 ad = reinterpret_cast<const float2*>(adst)[lane];
    float ps = hv.x * as.x + hv.y * as.y;
    float pd = hv.x * ad.x + hv.y * ad.y;
#pragma unroll
    for (int off = 16; off; off >>= 1) {
        ps += __shfl_xor_sync(0xffffffffu, ps, off);
        pd += __shfl_xor_sync(0xffffffffu, pd, off);
    }
    float ss = ps + pd;
    float w  = __expf(leaky(ss));
    reinterpret_cast<float2*>(g_acc0)[gw * 32 + lane] = make_float2(w * hv.x, w * hv.y);
    if (lane == 0) { g_ssrc0[gw] = ps; g_sdst0[gw] = pd; g_denom0[gw] = w; }
}

// ---------------- layer 0: edge aggregation (16 threads per edge) --------
__global__ void edge0_kernel(const int* __restrict__ ei, int E) {
    int t = blockIdx.x * blockDim.x + threadIdx.x;
    int e = t >> 4, l = t & 15;
    if (e >= E) return;
    int src = ei[e];
    int dst = ei[E + e];
    float ss = g_ssrc0[src] + g_sdst0[dst];
    float w  = __expf(leaky(ss));
    float4 hv = reinterpret_cast<const float4*>(g_h0)[src * 16 + l];
    red_add4(&g_acc0[dst * 64 + l * 4], make_float4(w * hv.x, w * hv.y, w * hv.z, w * hv.w));
    if (l == 0) atomicAdd(&g_denom0[dst], w);
}

// ---------------- layer 0: finalize (acc/denom + bias + skip, ELU) -------
__global__ void final0_kernel(const float* __restrict__ b0,
                              const float* __restrict__ sb0, int n) {
    int i = blockIdx.x * blockDim.x + threadIdx.x;
    if (i >= n * 16) return;
    int node = i >> 4, c4 = i & 15;
    float inv = 1.f / g_denom0[node];
    float4 a  = reinterpret_cast<const float4*>(g_acc0)[i];
    float4 s  = reinterpret_cast<const float4*>(g_skip0)[i];
    float4 bb = reinterpret_cast<const float4*>(b0)[c4];
    float4 sb = reinterpret_cast<const float4*>(sb0)[c4];
    float v0 = fmaf(a.x, inv, bb.x + sb.x + s.x);
    float v1 = fmaf(a.y, inv, bb.y + sb.y + s.y);
    float v2 = fmaf(a.z, inv, bb.z + sb.z + s.z);
    float v3 = fmaf(a.w, inv, bb.w + sb.w + s.w);
    float4 o;
    o.x = v0 > 0.f ? v0 : expm1f(v0);
    o.y = v1 > 0.f ? v1 : expm1f(v1);
    o.z = v2 > 0.f ? v2 : expm1f(v2);
    o.w = v3 > 0.f ? v3 : expm1f(v3);
    reinterpret_cast<float4*>(g_h1)[i] = o;
}

// ---------------- layer 1: per-node init (warp per node, C=32) -----------
__global__ void init1_kernel(const float* __restrict__ asrc,
                             const float* __restrict__ adst, int n) {
    int gw   = (blockIdx.x * blockDim.x + threadIdx.x) >> 5;
    int lane = threadIdx.x & 31;
    if (gw >= n) return;
    float hv = g_h1p[gw * 32 + lane];
    float ps = hv * asrc[lane];
    float pd = hv * adst[lane];
#pragma unroll
    for (int off = 16; off; off >>= 1) {
        ps += __shfl_xor_sync(0xffffffffu, ps, off);
        pd += __shfl_xor_sync(0xffffffffu, pd, off);
    }
    float ss = ps + pd;
    float w  = __expf(leaky(ss));
    g_acc1[gw * 32 + lane] = w * hv;
    if (lane == 0) { g_ssrc1[gw] = ps; g_sdst1[gw] = pd; g_denom1[gw] = w; }
}

// ---------------- layer 1: edge aggregation (8 threads per edge) ---------
__global__ void edge1_kernel(const int* __restrict__ ei, int E) {
    int t = blockIdx.x * blockDim.x + threadIdx.x;
    int e = t >> 3, l = t & 7;
    if (e >= E) return;
    int src = ei[e];
    int dst = ei[E + e];
    float ss = g_ssrc1[src] + g_sdst1[dst];
    float w  = __expf(leaky(ss));
    float4 hv = reinterpret_cast<const float4*>(g_h1p)[src * 8 + l];
    red_add4(&g_acc1[dst * 32 + l * 4], make_float4(w * hv.x, w * hv.y, w * hv.z, w * hv.w));
    if (l == 0) atomicAdd(&g_denom1[dst], w);
}

// ---------------- layer 1: finalize + log_softmax (warp per node) --------
__global__ void final1_kernel(const float* __restrict__ b1,
                              const float* __restrict__ sb1,
                              float* __restrict__ out, int n) {
    int gw   = (blockIdx.x * blockDim.x + threadIdx.x) >> 5;
    int lane = threadIdx.x & 31;
    if (gw >= n) return;
    float inv = 1.f / g_denom1[gw];
    float z = fmaf(g_acc1[gw * 32 + lane], inv,
                   b1[lane] + sb1[lane] + g_skip1[gw * 32 + lane]);
    float m = z;
#pragma unroll
    for (int off = 16; off; off >>= 1) m = fmaxf(m, __shfl_xor_sync(0xffffffffu, m, off));
    float ex = expf(z - m);
    float s  = ex;
#pragma unroll
    for (int off = 16; off; off >>= 1) s += __shfl_xor_sync(0xffffffffu, s, off);
    out[gw * 32 + lane] = z - m - logf(s);
}

// ---------------- host ----------------
extern "C" void kernel_launch(void* const* d_in, const int* in_sizes, int n_in,
                              void* d_out, int out_size) {
    const float* x     = (const float*)d_in[0];
    const int*   ei    = (const int*)  d_in[1];
    const float* W0    = (const float*)d_in[2];
    const float* asrc0 = (const float*)d_in[3];
    const float* adst0 = (const float*)d_in[4];
    const float* b0    = (const float*)d_in[5];
    const float* sW0   = (const float*)d_in[6];
    const float* sb0   = (const float*)d_in[7];
    const float* W1    = (const float*)d_in[8];
    const float* asrc1 = (const float*)d_in[9];
    const float* adst1 = (const float*)d_in[10];
    const float* b1    = (const float*)d_in[11];
    const float* sW1   = (const float*)d_in[12];
    const float* sb1   = (const float*)d_in[13];
    float* out = (float*)d_out;

    const int n = in_sizes[0] / 128;   // 100000
    const int E = in_sizes[1] / 2;     // 1600000

    float *h0p, *skip0p, *h1ptr, *h1pp, *skip1p;
    cudaGetSymbolAddress((void**)&h0p,    g_h0);
    cudaGetSymbolAddress((void**)&skip0p, g_skip0);
    cudaGetSymbolAddress((void**)&h1ptr,  g_h1);
    cudaGetSymbolAddress((void**)&h1pp,   g_h1p);
    cudaGetSymbolAddress((void**)&skip1p, g_skip1);

    const int nodeBlocks = (n * 32 + 255) / 256;   // warp-per-node kernels

    // ---- layer 0 ----
    gemm_dual<128, 128><<<(n + 31) / 32, 256>>>(x, W0, sW0, h0p, skip0p, n);
    init0_kernel<<<nodeBlocks, 256>>>(asrc0, adst0, n);
    edge0_kernel<<<(E * 16 + 255) / 256, 256>>>(ei, E);
    final0_kernel<<<(n * 16 + 255) / 256, 256>>>(b0, sb0, n);

    // ---- layer 1 ----
    gemm_dual<64, 64><<<(n + 31) / 32, 256>>>(h1ptr, W1, sW1, h1pp, skip1p, n);
    init1_kernel<<<nodeBlocks, 256>>>(asrc1, adst1, n);
    edge1_kernel<<<(E * 8 + 255) / 256, 256>>>(ei, E);
    final1_kernel<<<nodeBlocks, 256>>>(b1, sb1, out, n);
}

// round 2
// speedup vs baseline: 1.6189x; 1.6189x over previous
#include <cuda_runtime.h>
#include <math.h>

#define NODES 100000
#define MAXE  1600000

// ---------------- scratch (device globals; no allocation) ----------------
__device__ float g_h0[NODES * 64];     // x @ W0
__device__ float g_skip0[NODES * 64];  // x @ sW0
__device__ float g_ssrc0[NODES];
__device__ float g_sdst0[NODES];
__device__ float g_h1[NODES * 64];     // layer-1 input (post ELU)
__device__ float g_h1p[NODES * 32];    // h1 @ W1
__device__ float g_skip1[NODES * 32];  // h1 @ sW1
__device__ float g_ssrc1[NODES];
__device__ float g_sdst1[NODES];
// CSR build
__device__ int g_deg[NODES];
__device__ int g_off[NODES];
__device__ int g_pos[NODES];
__device__ int g_bsum[128];
__device__ int g_boff[128];
__device__ int g_esrc[MAXE];

__device__ __forceinline__ float leaky(float x) { return x > 0.f ? x : 0.2f * x; }

// ================= CSR build: histogram -> scan -> scatter =================
__global__ void hist_kernel(const int* __restrict__ ei, int E) {
    int e = blockIdx.x * blockDim.x + threadIdx.x;
    if (e < E) atomicAdd(&g_deg[ei[E + e]], 1);
}

__global__ __launch_bounds__(1024) void scan1_kernel(int n) {
    __shared__ int wsum[32];
    int t = threadIdx.x, i = blockIdx.x * 1024 + t;
    int v = (i < n) ? g_deg[i] : 0;
    int lane = t & 31, wid = t >> 5;
    int x = v;
#pragma unroll
    for (int o = 1; o < 32; o <<= 1) {
        int y = __shfl_up_sync(0xffffffffu, x, o);
        if (lane >= o) x += y;
    }
    if (lane == 31) wsum[wid] = x;
    __syncthreads();
    if (wid == 0) {
        int s = wsum[lane];
#pragma unroll
        for (int o = 1; o < 32; o <<= 1) {
            int y = __shfl_up_sync(0xffffffffu, s, o);
            if (lane >= o) s += y;
        }
        wsum[lane] = s;
    }
    __syncthreads();
    int pref = wid ? wsum[wid - 1] : 0;
    int incl = x + pref;
    if (i < n) g_off[i] = incl - v;       // exclusive within block
    if (t == 1023) g_bsum[blockIdx.x] = incl;
}

__global__ void scan2_kernel(int nb) {
    __shared__ int s[128];
    int t = threadIdx.x;
    s[t] = (t < nb) ? g_bsum[t] : 0;
    __syncthreads();
    if (t == 0) {
        int run = 0;
        for (int b = 0; b < nb; b++) { int tmp = s[b]; s[b] = run; run += tmp; }
    }
    __syncthreads();
    if (t < nb) g_boff[t] = s[t];
}

__global__ void scan3_kernel(int n) {
    int i = blockIdx.x * blockDim.x + threadIdx.x;
    if (i < n) {
        int o = g_off[i] + g_boff[i >> 10];
        g_off[i] = o;
        g_pos[i] = o;       // cursor; after scatter g_pos[i] == segment end
    }
}

__global__ void scatter_kernel(const int* __restrict__ ei, int E) {
    int e = blockIdx.x * blockDim.x + threadIdx.x;
    if (e < E) {
        int dst = ei[E + e];
        int p = atomicAdd(&g_pos[dst], 1);
        g_esrc[p] = ei[e];
    }
}

// ---------------- dual GEMM: O_a = X@Wa, O_b = X@Wb (both K x CT/2) -------
template<int K, int CT>
__global__ __launch_bounds__(256)
void gemm_dual(const float* __restrict__ X,
               const float* __restrict__ Wa,
               const float* __restrict__ Wb,
               float* __restrict__ Oa,
               float* __restrict__ Ob,
               int n) {
    constexpr int TR   = 32;
    constexpr int PAD  = TR + 4;
    constexpr int NCG  = CT / 4;
    constexpr int NRG  = 256 / NCG;
    constexpr int R    = TR / NRG;
    constexpr int HALF = CT / 2;

    __shared__ float xs[K * PAD];

    const int t    = threadIdx.x;
    const int base = blockIdx.x * TR;

    for (int i = t; i < TR * K; i += 256) {
        int r = i / K, k = i - r * K;
        xs[k * PAD + r] = X[(base + r) * K + k];
    }
    __syncthreads();

    const int  cg     = t % NCG;
    const int  rg     = t / NCG;
    const bool second = (cg >= NCG / 2);
    const float* Wsel = second ? Wb : Wa;
    const int  ccol   = (second ? (cg - NCG / 2) : cg) * 4;

    float acc[R][4];
#pragma unroll
    for (int j = 0; j < R; j++)
#pragma unroll
        for (int m = 0; m < 4; m++) acc[j][m] = 0.f;

    const float4* wp = reinterpret_cast<const float4*>(Wsel + ccol);

#pragma unroll 4
    for (int k = 0; k < K; k++) {
        float4 w = wp[k * (HALF / 4)];
        float  xr[R];
        if constexpr (R == 4) {
            float4 v = *reinterpret_cast<const float4*>(&xs[k * PAD + rg * 4]);
            xr[0] = v.x; xr[1] = v.y; xr[2] = v.z; xr[3] = v.w;
        } else {
            float2 v = *reinterpret_cast<const float2*>(&xs[k * PAD + rg * 2]);
            xr[0] = v.x; xr[1] = v.y;
        }
#pragma unroll
        for (int j = 0; j < R; j++) {
            acc[j][0] = fmaf(xr[j], w.x, acc[j][0]);
            acc[j][1] = fmaf(xr[j], w.y, acc[j][1]);
            acc[j][2] = fmaf(xr[j], w.z, acc[j][2]);
            acc[j][3] = fmaf(xr[j], w.w, acc[j][3]);
        }
    }

    float* O = second ? Ob : Oa;
#pragma unroll
    for (int j = 0; j < R; j++) {
        int row = base + rg * R + j;
        if (row < n) {
            float4 v = make_float4(acc[j][0], acc[j][1], acc[j][2], acc[j][3]);
            *reinterpret_cast<float4*>(&O[row * HALF + ccol]) = v;
        }
    }
}

// --------- attention score vectors: ssrc/sdst per node (warp/node) --------
__global__ void scomp0_kernel(const float* __restrict__ asrc,
                              const float* __restrict__ adst, int n) {
    int gw   = (blockIdx.x * blockDim.x + threadIdx.x) >> 5;
    int lane = threadIdx.x & 31;
    if (gw >= n) return;
    float2 hv = reinterpret_cast<const float2*>(g_h0)[gw * 32 + lane];
    float2 as = reinterpret_cast<const float2*>(asrc)[lane];
    float2 ad = reinterpret_cast<const float2*>(adst)[lane];
    float ps = hv.x * as.x + hv.y * as.y;
    float pd = hv.x * ad.x + hv.y * ad.y;
#pragma unroll
    for (int off = 16; off; off >>= 1) {
        ps += __shfl_xor_sync(0xffffffffu, ps, off);
        pd += __shfl_xor_sync(0xffffffffu, pd, off);
    }
    if (lane == 0) { g_ssrc0[gw] = ps; g_sdst0[gw] = pd; }
}

__global__ void scomp1_kernel(const float* __restrict__ asrc,
                              const float* __restrict__ adst, int n) {
    int gw   = (blockIdx.x * blockDim.x + threadIdx.x) >> 5;
    int lane = threadIdx.x & 31;
    if (gw >= n) return;
    float hv = g_h1p[gw * 32 + lane];
    float ps = hv * asrc[lane];
    float pd = hv * adst[lane];
#pragma unroll
    for (int off = 16; off; off >>= 1) {
        ps += __shfl_xor_sync(0xffffffffu, ps, off);
        pd += __shfl_xor_sync(0xffffffffu, pd, off);
    }
    if (lane == 0) { g_ssrc1[gw] = ps; g_sdst1[gw] = pd; }
}

// ------- layer 0 aggregation: warp/node, register acc, fused finalize -----
__global__ __launch_bounds__(256)
void agg0_kernel(const float* __restrict__ b0,
                 const float* __restrict__ sb0, int n) {
    int gw   = (blockIdx.x * blockDim.x + threadIdx.x) >> 5;
    int lane = threadIdx.x & 31;
    if (gw >= n) return;
    const float2* h2 = reinterpret_cast<const float2*>(g_h0);

    float sd = g_sdst0[gw];
    float ws = __expf(leaky(g_ssrc0[gw] + sd));      // self-loop
    float2 hs = h2[gw * 32 + lane];
    float ax = ws * hs.x, ay = ws * hs.y;
    float dlane = 0.f;

    int start = g_off[gw], end = g_pos[gw];
    for (int base = start; base < end; base += 32) {
        int j = base + lane;
        int s = 0; float w = 0.f;
        if (j < end) {
            s = g_esrc[j];
            w = __expf(leaky(g_ssrc0[s] + sd));
        }
        dlane += w;
        int cnt = end - base; if (cnt > 32) cnt = 32;
        for (int k = 0; k < cnt; k++) {
            int   sk = __shfl_sync(0xffffffffu, s, k);
            float wk = __shfl_sync(0xffffffffu, w, k);
            float2 hv = h2[sk * 32 + lane];
            ax = fmaf(wk, hv.x, ax);
            ay = fmaf(wk, hv.y, ay);
        }
    }
#pragma unroll
    for (int off = 16; off; off >>= 1)
        dlane += __shfl_xor_sync(0xffffffffu, dlane, off);
    float inv = 1.f / (dlane + ws);

    float2 sk2 = reinterpret_cast<const float2*>(g_skip0)[gw * 32 + lane];
    float2 bb  = reinterpret_cast<const float2*>(b0)[lane];
    float2 sb  = reinterpret_cast<const float2*>(sb0)[lane];
    float v0 = fmaf(ax, inv, bb.x + sb.x + sk2.x);
    float v1 = fmaf(ay, inv, bb.y + sb.y + sk2.y);
    float2 o2;
    o2.x = v0 > 0.f ? v0 : expm1f(v0);
    o2.y = v1 > 0.f ? v1 : expm1f(v1);
    reinterpret_cast<float2*>(g_h1)[gw * 32 + lane] = o2;
}

// --- layer 1 aggregation: warp/node, fused finalize + log_softmax ---------
__global__ __launch_bounds__(256)
void agg1_kernel(const float* __restrict__ b1,
                 const float* __restrict__ sb1,
                 float* __restrict__ out, int n) {
    int gw   = (blockIdx.x * blockDim.x + threadIdx.x) >> 5;
    int lane = threadIdx.x & 31;
    if (gw >= n) return;

    float sd = g_sdst1[gw];
    float ws = __expf(leaky(g_ssrc1[gw] + sd));
    float hsl = g_h1p[gw * 32 + lane];
    float acc = ws * hsl;
    float dlane = 0.f;

    int start = g_off[gw], end = g_pos[gw];
    for (int base = start; base < end; base += 32) {
        int j = base + lane;
        int s = 0; float w = 0.f;
        if (j < end) {
            s = g_esrc[j];
            w = __expf(leaky(g_ssrc1[s] + sd));
        }
        dlane += w;
        int cnt = end - base; if (cnt > 32) cnt = 32;
        for (int k = 0; k < cnt; k++) {
            int   sk = __shfl_sync(0xffffffffu, s, k);
            float wk = __shfl_sync(0xffffffffu, w, k);
            acc = fmaf(wk, g_h1p[sk * 32 + lane], acc);
        }
    }
#pragma unroll
    for (int off = 16; off; off >>= 1)
        dlane += __shfl_xor_sync(0xffffffffu, dlane, off);
    float inv = 1.f / (dlane + ws);

    float z = fmaf(acc, inv, b1[lane] + sb1[lane] + g_skip1[gw * 32 + lane]);
    float m = z;
#pragma unroll
    for (int off = 16; off; off >>= 1)
        m = fmaxf(m, __shfl_xor_sync(0xffffffffu, m, off));
    float ex = expf(z - m);
    float s = ex;
#pragma unroll
    for (int off = 16; off; off >>= 1)
        s += __shfl_xor_sync(0xffffffffu, s, off);
    out[gw * 32 + lane] = z - m - logf(s);
}

// ---------------- host ----------------
extern "C" void kernel_launch(void* const* d_in, const int* in_sizes, int n_in,
                              void* d_out, int out_size) {
    const float* x     = (const float*)d_in[0];
    const int*   ei    = (const int*)  d_in[1];
    const float* W0    = (const float*)d_in[2];
    const float* asrc0 = (const float*)d_in[3];
    const float* adst0 = (const float*)d_in[4];
    const float* b0    = (const float*)d_in[5];
    const float* sW0   = (const float*)d_in[6];
    const float* sb0   = (const float*)d_in[7];
    const float* W1    = (const float*)d_in[8];
    const float* asrc1 = (const float*)d_in[9];
    const float* adst1 = (const float*)d_in[10];
    const float* b1    = (const float*)d_in[11];
    const float* sb1   = (const float*)d_in[12] ? (const float*)d_in[13] : (const float*)d_in[13];
    const float* sW1   = (const float*)d_in[12];
    sb1 = (const float*)d_in[13];
    float* out = (float*)d_out;

    const int n = in_sizes[0] / 128;   // 100000
    const int E = in_sizes[1] / 2;     // 1600000

    float *h0p, *skip0p, *h1ptr, *h1pp, *skip1p;
    int *degp;
    cudaGetSymbolAddress((void**)&h0p,    g_h0);
    cudaGetSymbolAddress((void**)&skip0p, g_skip0);
    cudaGetSymbolAddress((void**)&h1ptr,  g_h1);
    cudaGetSymbolAddress((void**)&h1pp,   g_h1p);
    cudaGetSymbolAddress((void**)&skip1p, g_skip1);
    cudaGetSymbolAddress((void**)&degp,   g_deg);

    const int nodeBlocks = (n * 32 + 255) / 256;
    const int nb = (n + 1023) / 1024;

    // ---- CSR build (dst counting sort) ----
    cudaMemsetAsync(degp, 0, n * sizeof(int));
    hist_kernel<<<(E + 255) / 256, 256>>>(ei, E);
    scan1_kernel<<<nb, 1024>>>(n);
    scan2_kernel<<<1, 128>>>(nb);
    scan3_kernel<<<(n + 255) / 256, 256>>>(n);
    scatter_kernel<<<(E + 255) / 256, 256>>>(ei, E);

    // ---- layer 0 ----
    gemm_dual<128, 128><<<(n + 31) / 32, 256>>>(x, W0, sW0, h0p, skip0p, n);
    scomp0_kernel<<<nodeBlocks, 256>>>(asrc0, adst0, n);
    agg0_kernel<<<nodeBlocks, 256>>>(b0, sb0, n);

    // ---- layer 1 ----
    gemm_dual<64, 64><<<(n + 31) / 32, 256>>>(h1ptr, W1, sW1, h1pp, skip1p, n);
    scomp1_kernel<<<nodeBlocks, 256>>>(asrc1, adst1, n);
    agg1_kernel<<<nodeBlocks, 256>>>(b1, sb1, out, n);
}

// round 4
// speedup vs baseline: 3.0893x; 1.9082x over previous
#include <cuda_runtime.h>
#include <cuda_bf16.h>
#include <math.h>
#include <stdint.h>

#define NODES 100000
#define MAXE  1600000

// ---------------- scratch (device globals; no allocation) ----------------
__device__ float g_h0[NODES * 64];
__device__ float g_skip0[NODES * 64];
__device__ float g_ssrc0[NODES];
__device__ float g_sdst0[NODES];
__device__ float g_h1[NODES * 64];
__device__ float g_h1p[NODES * 32];
__device__ float g_skip1[NODES * 32];
__device__ float g_ssrc1[NODES];
__device__ float g_sdst1[NODES];
__device__ int g_deg[NODES];
__device__ int g_off[NODES];
__device__ int g_pos[NODES];
__device__ int g_bsum[128];
__device__ int g_boff[128];
__device__ int g_esrc[MAXE];
// B fragments in mma lane order: [kstep][ntile][lane] = {h0,h1,l0,l1}
__device__ uint4 g_Bf0[8 * 16 * 32];   // layer0: K=128 (8 ks), N=128 (16 nt)
__device__ uint4 g_Bf1[4 * 8 * 32];    // layer1: K=64  (4 ks), N=64  (8 nt)

__device__ __forceinline__ float leaky(float x) { return x > 0.f ? x : 0.2f * x; }

// ---------------- bf16 split helpers ----------------
__device__ __forceinline__ uint32_t pack_hi(float a, float b) {
    __nv_bfloat162 h = __floats2bfloat162_rn(a, b);
    return *reinterpret_cast<uint32_t*>(&h);
}
__device__ __forceinline__ uint32_t pack_lo(float a, float b) {
    float ha = __bfloat162float(__float2bfloat16(a));
    float hb = __bfloat162float(__float2bfloat16(b));
    __nv_bfloat162 l = __floats2bfloat162_rn(a - ha, b - hb);
    return *reinterpret_cast<uint32_t*>(&l);
}

__device__ __forceinline__ void mma16816(float* c, const uint32_t* a,
                                         uint32_t b0, uint32_t b1) {
    asm volatile("mma.sync.aligned.m16n8k16.row.col.f32.bf16.bf16.f32 "
                 "{%0,%1,%2,%3}, {%4,%5,%6,%7}, {%8,%9}, {%0,%1,%2,%3};"
                 : "+f"(c[0]), "+f"(c[1]), "+f"(c[2]), "+f"(c[3])
                 : "r"(a[0]), "r"(a[1]), "r"(a[2]), "r"(a[3]), "r"(b0), "r"(b1));
}

// ============ weight fragment prep (hi/lo split, mma lane order) ==========
__global__ void prep_w(const float* __restrict__ W0, const float* __restrict__ sW0,
                       const float* __restrict__ W1, const float* __restrict__ sW1) {
    int t = blockIdx.x * blockDim.x + threadIdx.x;
    int nt_ = gridDim.x * blockDim.x;
    // layer 0: idx = (ks*16 + nt)*32 + lane
    for (int idx = t; idx < 8 * 16 * 32; idx += nt_) {
        int lane = idx & 31, rest = idx >> 5;
        int ntile = rest & 15, ks = rest >> 4;
        int nn = ntile * 8 + (lane >> 2);
        int k0 = ks * 16 + (lane & 3) * 2;
        const float* Wc = (nn < 64) ? W0 : sW0;
        int c = nn & 63;
        float w00 = Wc[k0 * 64 + c],       w01 = Wc[(k0 + 1) * 64 + c];
        float w10 = Wc[(k0 + 8) * 64 + c], w11 = Wc[(k0 + 9) * 64 + c];
        g_Bf0[idx] = make_uint4(pack_hi(w00, w01), pack_hi(w10, w11),
                                pack_lo(w00, w01), pack_lo(w10, w11));
    }
    // layer 1
    for (int idx = t; idx < 4 * 8 * 32; idx += nt_) {
        int lane = idx & 31, rest = idx >> 5;
        int ntile = rest & 7, ks = rest >> 3;
        int nn = ntile * 8 + (lane >> 2);
        int k0 = ks * 16 + (lane & 3) * 2;
        const float* Wc = (nn < 32) ? W1 : sW1;
        int c = nn & 31;
        float w00 = Wc[k0 * 32 + c],       w01 = Wc[(k0 + 1) * 32 + c];
        float w10 = Wc[(k0 + 8) * 32 + c], w11 = Wc[(k0 + 9) * 32 + c];
        g_Bf1[idx] = make_uint4(pack_hi(w00, w01), pack_hi(w10, w11),
                                pack_lo(w00, w01), pack_lo(w10, w11));
    }
}

// ================= CSR build: histogram -> scan -> scatter =================
__global__ void hist_kernel(const int* __restrict__ ei, int E) {
    int e = blockIdx.x * blockDim.x + threadIdx.x;
    if (e < E) atomicAdd(&g_deg[ei[E + e]], 1);
}

__global__ __launch_bounds__(1024) void scan1_kernel(int n) {
    __shared__ int wsum[32];
    int t = threadIdx.x, i = blockIdx.x * 1024 + t;
    int v = (i < n) ? g_deg[i] : 0;
    int lane = t & 31, wid = t >> 5;
    int x = v;
#pragma unroll
    for (int o = 1; o < 32; o <<= 1) {
        int y = __shfl_up_sync(0xffffffffu, x, o);
        if (lane >= o) x += y;
    }
    if (lane == 31) wsum[wid] = x;
    __syncthreads();
    if (wid == 0) {
        int s = wsum[lane];
#pragma unroll
        for (int o = 1; o < 32; o <<= 1) {
            int y = __shfl_up_sync(0xffffffffu, s, o);
            if (lane >= o) s += y;
        }
        wsum[lane] = s;
    }
    __syncthreads();
    int pref = wid ? wsum[wid - 1] : 0;
    int incl = x + pref;
    if (i < n) g_off[i] = incl - v;
    if (t == 1023) g_bsum[blockIdx.x] = incl;
}

__global__ void scan2_kernel(int nb) {
    __shared__ int s[128];
    int t = threadIdx.x;
    s[t] = (t < nb) ? g_bsum[t] : 0;
    __syncthreads();
    if (t == 0) {
        int run = 0;
        for (int b = 0; b < nb; b++) { int tmp = s[b]; s[b] = run; run += tmp; }
    }
    __syncthreads();
    if (t < nb) g_boff[t] = s[t];
}

__global__ void scan3_kernel(int n) {
    int i = blockIdx.x * blockDim.x + threadIdx.x;
    if (i < n) {
        int o = g_off[i] + g_boff[i >> 10];
        g_off[i] = o;
        g_pos[i] = o;
        g_deg[i] = 0;    // reset for next graph replay (hist accumulates)
    }
}

__global__ void scatter_kernel(const int* __restrict__ ei, int E) {
    int e = blockIdx.x * blockDim.x + threadIdx.x;
    if (e < E) {
        int dst = ei[E + e];
        int p = atomicAdd(&g_pos[dst], 1);
        g_esrc[p] = ei[e];
    }
}

// ====== layer0 GEMM via mma.sync bf16 (3-pass split) + fused scomp ========
// CTA: 256 thr = 4 M-warps x 2 N-warps. Tile M=128, N=128, K=128.
__global__ __launch_bounds__(256)
void gemm0_mma(const float* __restrict__ X,
               const float* __restrict__ avs, const float* __restrict__ avd, int n) {
    int tid = threadIdx.x, lane = tid & 31, warp = tid >> 5;
    int mwarp = warp & 3, nhalf = warp >> 2;
    int rowbase = blockIdx.x * 128 + mwarp * 32;
    int group = lane >> 2, qk = (lane & 3) * 2;

    float C[8][2][4];
#pragma unroll
    for (int a = 0; a < 8; a++)
#pragma unroll
        for (int b = 0; b < 2; b++)
#pragma unroll
            for (int c = 0; c < 4; c++) C[a][b][c] = 0.f;

#pragma unroll 1
    for (int ks = 0; ks < 8; ks++) {
        uint32_t ah[2][4], al[2][4];
#pragma unroll
        for (int mt = 0; mt < 2; mt++) {
            int r0 = rowbase + mt * 16 + group;
            int r1 = r0 + 8;
            int k0 = ks * 16 + qk;
            float2 z = make_float2(0.f, 0.f);
            float2 x00 = (r0 < n) ? *(const float2*)(X + (size_t)r0 * 128 + k0) : z;
            float2 x01 = (r0 < n) ? *(const float2*)(X + (size_t)r0 * 128 + k0 + 8) : z;
            float2 x10 = (r1 < n) ? *(const float2*)(X + (size_t)r1 * 128 + k0) : z;
            float2 x11 = (r1 < n) ? *(const float2*)(X + (size_t)r1 * 128 + k0 + 8) : z;
            ah[mt][0] = pack_hi(x00.x, x00.y); al[mt][0] = pack_lo(x00.x, x00.y);
            ah[mt][1] = pack_hi(x10.x, x10.y); al[mt][1] = pack_lo(x10.x, x10.y);
            ah[mt][2] = pack_hi(x01.x, x01.y); al[mt][2] = pack_lo(x01.x, x01.y);
            ah[mt][3] = pack_hi(x11.x, x11.y); al[mt][3] = pack_lo(x11.x, x11.y);
        }
        const uint4* bp = g_Bf0 + ((ks * 16 + nhalf * 8) * 32 + lane);
#pragma unroll
        for (int nt = 0; nt < 8; nt++) {
            uint4 B = bp[nt * 32];
#pragma unroll
            for (int mt = 0; mt < 2; mt++) {
                mma16816(C[nt][mt], ah[mt], B.x, B.y);   // hi*hi
                mma16816(C[nt][mt], al[mt], B.x, B.y);   // lo*hi
                mma16816(C[nt][mt], ah[mt], B.z, B.w);   // hi*lo
            }
        }
    }

    float* OUT = nhalf ? g_skip0 : g_h0;
#pragma unroll
    for (int mt = 0; mt < 2; mt++)
#pragma unroll
        for (int rr = 0; rr < 2; rr++) {
            int row = rowbase + mt * 16 + group + rr * 8;
            float ss = 0.f, sd = 0.f;
#pragma unroll
            for (int nt = 0; nt < 8; nt++) {
                float c0 = C[nt][mt][rr * 2], c1 = C[nt][mt][rr * 2 + 1];
                int col = nt * 8 + qk;
                if (row < n)
                    *(float2*)(OUT + (size_t)row * 64 + col) = make_float2(c0, c1);
                if (nhalf == 0) {
                    ss = fmaf(c0, __ldg(avs + col), fmaf(c1, __ldg(avs + col + 1), ss));
                    sd = fmaf(c0, __ldg(avd + col), fmaf(c1, __ldg(avd + col + 1), sd));
                }
            }
            if (nhalf == 0) {
                ss += __shfl_xor_sync(0xffffffffu, ss, 1);
                ss += __shfl_xor_sync(0xffffffffu, ss, 2);
                sd += __shfl_xor_sync(0xffffffffu, sd, 1);
                sd += __shfl_xor_sync(0xffffffffu, sd, 2);
                if ((lane & 3) == 0 && row < n) { g_ssrc0[row] = ss; g_sdst0[row] = sd; }
            }
        }
}

// ====== layer1 GEMM via mma.sync + fused scomp ============================
// CTA: 128 thr = 4 M-warps. Tile M=128, N=64, K=64.
__global__ __launch_bounds__(128)
void gemm1_mma(const float* __restrict__ X,
               const float* __restrict__ avs, const float* __restrict__ avd, int n) {
    int tid = threadIdx.x, lane = tid & 31, mwarp = tid >> 5;
    int rowbase = blockIdx.x * 128 + mwarp * 32;
    int group = lane >> 2, qk = (lane & 3) * 2;

    float C[8][2][4];
#pragma unroll
    for (int a = 0; a < 8; a++)
#pragma unroll
        for (int b = 0; b < 2; b++)
#pragma unroll
            for (int c = 0; c < 4; c++) C[a][b][c] = 0.f;

#pragma unroll 1
    for (int ks = 0; ks < 4; ks++) {
        uint32_t ah[2][4], al[2][4];
#pragma unroll
        for (int mt = 0; mt < 2; mt++) {
            int r0 = rowbase + mt * 16 + group;
            int r1 = r0 + 8;
            int k0 = ks * 16 + qk;
            float2 z = make_float2(0.f, 0.f);
            float2 x00 = (r0 < n) ? *(const float2*)(X + (size_t)r0 * 64 + k0) : z;
            float2 x01 = (r0 < n) ? *(const float2*)(X + (size_t)r0 * 64 + k0 + 8) : z;
            float2 x10 = (r1 < n) ? *(const float2*)(X + (size_t)r1 * 64 + k0) : z;
            float2 x11 = (r1 < n) ? *(const float2*)(X + (size_t)r1 * 64 + k0 + 8) : z;
            ah[mt][0] = pack_hi(x00.x, x00.y); al[mt][0] = pack_lo(x00.x, x00.y);
            ah[mt][1] = pack_hi(x10.x, x10.y); al[mt][1] = pack_lo(x10.x, x10.y);
            ah[mt][2] = pack_hi(x01.x, x01.y); al[mt][2] = pack_lo(x01.x, x01.y);
            ah[mt][3] = pack_hi(x11.x, x11.y); al[mt][3] = pack_lo(x11.x, x11.y);
        }
        const uint4* bp = g_Bf1 + ((ks * 8) * 32 + lane);
#pragma unroll
        for (int nt = 0; nt < 8; nt++) {
            uint4 B = bp[nt * 32];
#pragma unroll
            for (int mt = 0; mt < 2; mt++) {
                mma16816(C[nt][mt], ah[mt], B.x, B.y);
                mma16816(C[nt][mt], al[mt], B.x, B.y);
                mma16816(C[nt][mt], ah[mt], B.z, B.w);
            }
        }
    }

#pragma unroll
    for (int mt = 0; mt < 2; mt++)
#pragma unroll
        for (int rr = 0; rr < 2; rr++) {
            int row = rowbase + mt * 16 + group + rr * 8;
            float ss = 0.f, sd = 0.f;
#pragma unroll
            for (int nt = 0; nt < 8; nt++) {
                float c0 = C[nt][mt][rr * 2], c1 = C[nt][mt][rr * 2 + 1];
                int col = nt * 8 + qk;
                if (row < n) {
                    if (nt < 4)
                        *(float2*)(g_h1p + (size_t)row * 32 + col) = make_float2(c0, c1);
                    else
                        *(float2*)(g_skip1 + (size_t)row * 32 + col - 32) = make_float2(c0, c1);
                }
                if (nt < 4) {
                    ss = fmaf(c0, __ldg(avs + col), fmaf(c1, __ldg(avs + col + 1), ss));
                    sd = fmaf(c0, __ldg(avd + col), fmaf(c1, __ldg(avd + col + 1), sd));
                }
            }
            ss += __shfl_xor_sync(0xffffffffu, ss, 1);
            ss += __shfl_xor_sync(0xffffffffu, ss, 2);
            sd += __shfl_xor_sync(0xffffffffu, sd, 1);
            sd += __shfl_xor_sync(0xffffffffu, sd, 2);
            if ((lane & 3) == 0 && row < n) { g_ssrc1[row] = ss; g_sdst1[row] = sd; }
        }
}

// ------- layer 0 aggregation: warp/node, register acc, fused finalize -----
__global__ __launch_bounds__(256)
void agg0_kernel(const float* __restrict__ b0,
                 const float* __restrict__ sb0, int n) {
    int gw   = (blockIdx.x * blockDim.x + threadIdx.x) >> 5;
    int lane = threadIdx.x & 31;
    if (gw >= n) return;
    const float2* h2 = reinterpret_cast<const float2*>(g_h0);

    float sd = g_sdst0[gw];
    float ws = __expf(leaky(g_ssrc0[gw] + sd));
    float2 hs = h2[gw * 32 + lane];
    float ax = ws * hs.x, ay = ws * hs.y;
    float dlane = 0.f;

    int start = g_off[gw], end = g_pos[gw];
    for (int base = start; base < end; base += 32) {
        int j = base + lane;
        int s = 0; float w = 0.f;
        if (j < end) {
            s = g_esrc[j];
            w = __expf(leaky(g_ssrc0[s] + sd));
        }
        dlane += w;
        int cnt = end - base; if (cnt > 32) cnt = 32;
        for (int k = 0; k < cnt; k++) {
            int   sk = __shfl_sync(0xffffffffu, s, k);
            float wk = __shfl_sync(0xffffffffu, w, k);
            float2 hv = h2[sk * 32 + lane];
            ax = fmaf(wk, hv.x, ax);
            ay = fmaf(wk, hv.y, ay);
        }
    }
#pragma unroll
    for (int off = 16; off; off >>= 1)
        dlane += __shfl_xor_sync(0xffffffffu, dlane, off);
    float inv = 1.f / (dlane + ws);

    float2 sk2 = reinterpret_cast<const float2*>(g_skip0)[gw * 32 + lane];
    float2 bb  = reinterpret_cast<const float2*>(b0)[lane];
    float2 sbv = reinterpret_cast<const float2*>(sb0)[lane];
    float v0 = fmaf(ax, inv, bb.x + sbv.x + sk2.x);
    float v1 = fmaf(ay, inv, bb.y + sbv.y + sk2.y);
    float2 o2;
    o2.x = v0 > 0.f ? v0 : expm1f(v0);
    o2.y = v1 > 0.f ? v1 : expm1f(v1);
    reinterpret_cast<float2*>(g_h1)[gw * 32 + lane] = o2;
}

// --- layer 1 aggregation: warp/node, fused finalize + log_softmax ---------
__global__ __launch_bounds__(256)
void agg1_kernel(const float* __restrict__ b1,
                 const float* __restrict__ sb1,
                 float* __restrict__ out, int n) {
    int gw   = (blockIdx.x * blockDim.x + threadIdx.x) >> 5;
    int lane = threadIdx.x & 31;
    if (gw >= n) return;

    float sd = g_sdst1[gw];
    float ws = __expf(leaky(g_ssrc1[gw] + sd));
    float hsl = g_h1p[gw * 32 + lane];
    float acc = ws * hsl;
    float dlane = 0.f;

    int start = g_off[gw], end = g_pos[gw];
    for (int base = start; base < end; base += 32) {
        int j = base + lane;
        int s = 0; float w = 0.f;
        if (j < end) {
            s = g_esrc[j];
            w = __expf(leaky(g_ssrc1[s] + sd));
        }
        dlane += w;
        int cnt = end - base; if (cnt > 32) cnt = 32;
        for (int k = 0; k < cnt; k++) {
            int   sk = __shfl_sync(0xffffffffu, s, k);
            float wk = __shfl_sync(0xffffffffu, w, k);
            acc = fmaf(wk, g_h1p[sk * 32 + lane], acc);
        }
    }
#pragma unroll
    for (int off = 16; off; off >>= 1)
        dlane += __shfl_xor_sync(0xffffffffu, dlane, off);
    float inv = 1.f / (dlane + ws);

    float z = fmaf(acc, inv, b1[lane] + sb1[lane] + g_skip1[gw * 32 + lane]);
    float m = z;
#pragma unroll
    for (int off = 16; off; off >>= 1)
        m = fmaxf(m, __shfl_xor_sync(0xffffffffu, m, off));
    float ex = expf(z - m);
    float s = ex;
#pragma unroll
    for (int off = 16; off; off >>= 1)
        s += __shfl_xor_sync(0xffffffffu, s, off);
    out[gw * 32 + lane] = z - m - logf(s);
}

// ---------------- host ----------------
extern "C" void kernel_launch(void* const* d_in, const int* in_sizes, int n_in,
                              void* d_out, int out_size) {
    const float* x     = (const float*)d_in[0];
    const int*   ei    = (const int*)  d_in[1];
    const float* W0    = (const float*)d_in[2];
    const float* asrc0 = (const float*)d_in[3];
    const float* adst0 = (const float*)d_in[4];
    const float* b0    = (const float*)d_in[5];
    const float* sW0   = (const float*)d_in[6];
    const float* sb0   = (const float*)d_in[7];
    const float* W1    = (const float*)d_in[8];
    const float* asrc1 = (const float*)d_in[9];
    const float* adst1 = (const float*)d_in[10];
    const float* b1    = (const float*)d_in[11];
    const float* sW1   = (const float*)d_in[12];
    const float* sb1   = (const float*)d_in[13];
    float* out = (float*)d_out;

    const int n = in_sizes[0] / 128;   // 100000
    const int E = in_sizes[1] / 2;     // 1600000

    float *h1ptr;
    cudaGetSymbolAddress((void**)&h1ptr, g_h1);

    const int nodeBlocks = (n * 32 + 255) / 256;
    const int nb = (n + 1023) / 1024;
    const int gemmBlocks = (n + 127) / 128;

    // ---- prep + CSR build (g_deg is zeroed by scan3 of the previous replay;
    //      zero-initialized device globals cover the very first run) ----
    prep_w<<<40, 256>>>(W0, sW0, W1, sW1);
    hist_kernel<<<(E + 255) / 256, 256>>>(ei, E);
    scan1_kernel<<<nb, 1024>>>(n);
    scan2_kernel<<<1, 128>>>(nb);
    scan3_kernel<<<(n + 255) / 256, 256>>>(n);
    scatter_kernel<<<(E + 255) / 256, 256>>>(ei, E);

    // ---- layer 0 ----
    gemm0_mma<<<gemmBlocks, 256>>>(x, asrc0, adst0, n);
    agg0_kernel<<<nodeBlocks, 256>>>(b0, sb0, n);

    // ---- layer 1 ----
    gemm1_mma<<<gemmBlocks, 128>>>(h1ptr, asrc1, adst1, n);
    agg1_kernel<<<nodeBlocks, 256>>>(b1, sb1, out, n);
}

// round 5
// speedup vs baseline: 3.2654x; 1.0570x over previous
#include <cuda_runtime.h>
#include <cuda_bf16.h>
#include <math.h>
#include <stdint.h>

#define NODES 100000
#define MAXE  1600000

// ---------------- scratch (device globals; no allocation) ----------------
__device__ float g_h0[NODES * 64];
__device__ float g_skip0[NODES * 64];
__device__ float g_ssrc0[NODES];
__device__ float g_sdst0[NODES];
__device__ float g_h1[NODES * 64];
__device__ float g_h1p[NODES * 32];
__device__ float g_skip1[NODES * 32];
__device__ float g_ssrc1[NODES];
__device__ float g_sdst1[NODES];
__device__ int g_deg[NODES];
__device__ int g_off[NODES];
__device__ int g_pos[NODES];
__device__ int g_bsum[128];
__device__ int g_boff[128];
__device__ int g_esrc[MAXE];
// B fragments in mma lane order: [kstep][ntile][lane] = {h0,h1,l0,l1}
__device__ uint4 g_Bf0[8 * 16 * 32];   // layer0: K=128 (8 ks), N=128 (16 nt)
__device__ uint4 g_Bf1[4 * 8 * 32];    // layer1: K=64  (4 ks), N=64  (8 nt)

__device__ __forceinline__ float leaky(float x) { return x > 0.f ? x : 0.2f * x; }

// ---------------- bf16 split helpers ----------------
__device__ __forceinline__ uint32_t pack_hi(float a, float b) {
    __nv_bfloat162 h = __floats2bfloat162_rn(a, b);
    return *reinterpret_cast<uint32_t*>(&h);
}
__device__ __forceinline__ uint32_t pack_lo(float a, float b) {
    float ha = __bfloat162float(__float2bfloat16(a));
    float hb = __bfloat162float(__float2bfloat16(b));
    __nv_bfloat162 l = __floats2bfloat162_rn(a - ha, b - hb);
    return *reinterpret_cast<uint32_t*>(&l);
}

__device__ __forceinline__ void mma16816(float* c, const uint32_t* a,
                                         uint32_t b0, uint32_t b1) {
    asm volatile("mma.sync.aligned.m16n8k16.row.col.f32.bf16.bf16.f32 "
                 "{%0,%1,%2,%3}, {%4,%5,%6,%7}, {%8,%9}, {%0,%1,%2,%3};"
                 : "+f"(c[0]), "+f"(c[1]), "+f"(c[2]), "+f"(c[3])
                 : "r"(a[0]), "r"(a[1]), "r"(a[2]), "r"(a[3]), "r"(b0), "r"(b1));
}

// ============ weight fragment prep (hi/lo split, mma lane order) ==========
__global__ void prep_w(const float* __restrict__ W0, const float* __restrict__ sW0,
                       const float* __restrict__ W1, const float* __restrict__ sW1) {
    int t = blockIdx.x * blockDim.x + threadIdx.x;
    int nt_ = gridDim.x * blockDim.x;
    for (int idx = t; idx < 8 * 16 * 32; idx += nt_) {
        int lane = idx & 31, rest = idx >> 5;
        int ntile = rest & 15, ks = rest >> 4;
        int nn = ntile * 8 + (lane >> 2);
        int k0 = ks * 16 + (lane & 3) * 2;
        const float* Wc = (nn < 64) ? W0 : sW0;
        int c = nn & 63;
        float w00 = Wc[k0 * 64 + c],       w01 = Wc[(k0 + 1) * 64 + c];
        float w10 = Wc[(k0 + 8) * 64 + c], w11 = Wc[(k0 + 9) * 64 + c];
        g_Bf0[idx] = make_uint4(pack_hi(w00, w01), pack_hi(w10, w11),
                                pack_lo(w00, w01), pack_lo(w10, w11));
    }
    for (int idx = t; idx < 4 * 8 * 32; idx += nt_) {
        int lane = idx & 31, rest = idx >> 5;
        int ntile = rest & 7, ks = rest >> 3;
        int nn = ntile * 8 + (lane >> 2);
        int k0 = ks * 16 + (lane & 3) * 2;
        const float* Wc = (nn < 32) ? W1 : sW1;
        int c = nn & 31;
        float w00 = Wc[k0 * 32 + c],       w01 = Wc[(k0 + 1) * 32 + c];
        float w10 = Wc[(k0 + 8) * 32 + c], w11 = Wc[(k0 + 9) * 32 + c];
        g_Bf1[idx] = make_uint4(pack_hi(w00, w01), pack_hi(w10, w11),
                                pack_lo(w00, w01), pack_lo(w10, w11));
    }
}

// ================= CSR build: histogram -> scan -> scatter =================
__global__ void hist_kernel(const int* __restrict__ ei, int E) {
    int t = blockIdx.x * blockDim.x + threadIdx.x;
    int e = t * 4;
    if (e + 3 < E) {
        int4 d = *(const int4*)(ei + E + e);
        atomicAdd(&g_deg[d.x], 1);
        atomicAdd(&g_deg[d.y], 1);
        atomicAdd(&g_deg[d.z], 1);
        atomicAdd(&g_deg[d.w], 1);
    } else {
        for (int k = e; k < E; k++) atomicAdd(&g_deg[ei[E + k]], 1);
    }
}

__global__ __launch_bounds__(1024) void scan1_kernel(int n) {
    __shared__ int wsum[32];
    int t = threadIdx.x, i = blockIdx.x * 1024 + t;
    int v = (i < n) ? g_deg[i] : 0;
    int lane = t & 31, wid = t >> 5;
    int x = v;
#pragma unroll
    for (int o = 1; o < 32; o <<= 1) {
        int y = __shfl_up_sync(0xffffffffu, x, o);
        if (lane >= o) x += y;
    }
    if (lane == 31) wsum[wid] = x;
    __syncthreads();
    if (wid == 0) {
        int s = wsum[lane];
#pragma unroll
        for (int o = 1; o < 32; o <<= 1) {
            int y = __shfl_up_sync(0xffffffffu, s, o);
            if (lane >= o) s += y;
        }
        wsum[lane] = s;
    }
    __syncthreads();
    int pref = wid ? wsum[wid - 1] : 0;
    int incl = x + pref;
    if (i < n) g_off[i] = incl - v;
    if (t == 1023) g_bsum[blockIdx.x] = incl;
}

// parallel exclusive scan of up to 128 block sums (4 warps + tiny combine)
__global__ void scan2_kernel(int nb) {
    __shared__ int ws[4];
    int t = threadIdx.x, lane = t & 31, wid = t >> 5;
    int v = (t < nb) ? g_bsum[t] : 0;
    int x = v;
#pragma unroll
    for (int o = 1; o < 32; o <<= 1) {
        int y = __shfl_up_sync(0xffffffffu, x, o);
        if (lane >= o) x += y;
    }
    if (lane == 31) ws[wid] = x;
    __syncthreads();
    int add = 0;
    for (int w = 0; w < wid; w++) add += ws[w];
    if (t < nb) g_boff[t] = x - v + add;
}

__global__ void scan3_kernel(int n) {
    int i = blockIdx.x * blockDim.x + threadIdx.x;
    if (i < n) {
        int o = g_off[i] + g_boff[i >> 10];
        g_off[i] = o;
        g_pos[i] = o;
        g_deg[i] = 0;    // reset for next replay
    }
}

__global__ void scatter_kernel(const int* __restrict__ ei, int E) {
    int t = blockIdx.x * blockDim.x + threadIdx.x;
    int e = t * 2;
    if (e + 1 < E) {
        int2 s2 = *(const int2*)(ei + e);
        int2 d2 = *(const int2*)(ei + E + e);
        int p0 = atomicAdd(&g_pos[d2.x], 1);
        int p1 = atomicAdd(&g_pos[d2.y], 1);
        g_esrc[p0] = s2.x;
        g_esrc[p1] = s2.y;
    } else if (e < E) {
        int p = atomicAdd(&g_pos[ei[E + e]], 1);
        g_esrc[p] = ei[e];
    }
}

// ====== layer0 GEMM via mma.sync bf16 (3-pass split) + fused scomp ========
__global__ __launch_bounds__(256)
void gemm0_mma(const float* __restrict__ X,
               const float* __restrict__ avs, const float* __restrict__ avd, int n) {
    int tid = threadIdx.x, lane = tid & 31, warp = tid >> 5;
    int mwarp = warp & 3, nhalf = warp >> 2;
    int rowbase = blockIdx.x * 128 + mwarp * 32;
    int group = lane >> 2, qk = (lane & 3) * 2;

    float C[8][2][4];
#pragma unroll
    for (int a = 0; a < 8; a++)
#pragma unroll
        for (int b = 0; b < 2; b++)
#pragma unroll
            for (int c = 0; c < 4; c++) C[a][b][c] = 0.f;

#pragma unroll 1
    for (int ks = 0; ks < 8; ks++) {
        uint32_t ah[2][4], al[2][4];
#pragma unroll
        for (int mt = 0; mt < 2; mt++) {
            int r0 = rowbase + mt * 16 + group;
            int r1 = r0 + 8;
            int k0 = ks * 16 + qk;
            float2 z = make_float2(0.f, 0.f);
            float2 x00 = (r0 < n) ? *(const float2*)(X + (size_t)r0 * 128 + k0) : z;
            float2 x01 = (r0 < n) ? *(const float2*)(X + (size_t)r0 * 128 + k0 + 8) : z;
            float2 x10 = (r1 < n) ? *(const float2*)(X + (size_t)r1 * 128 + k0) : z;
            float2 x11 = (r1 < n) ? *(const float2*)(X + (size_t)r1 * 128 + k0 + 8) : z;
            ah[mt][0] = pack_hi(x00.x, x00.y); al[mt][0] = pack_lo(x00.x, x00.y);
            ah[mt][1] = pack_hi(x10.x, x10.y); al[mt][1] = pack_lo(x10.x, x10.y);
            ah[mt][2] = pack_hi(x01.x, x01.y); al[mt][2] = pack_lo(x01.x, x01.y);
            ah[mt][3] = pack_hi(x11.x, x11.y); al[mt][3] = pack_lo(x11.x, x11.y);
        }
        const uint4* bp = g_Bf0 + ((ks * 16 + nhalf * 8) * 32 + lane);
#pragma unroll
        for (int nt = 0; nt < 8; nt++) {
            uint4 B = bp[nt * 32];
#pragma unroll
            for (int mt = 0; mt < 2; mt++) {
                mma16816(C[nt][mt], ah[mt], B.x, B.y);
                mma16816(C[nt][mt], al[mt], B.x, B.y);
                mma16816(C[nt][mt], ah[mt], B.z, B.w);
            }
        }
    }

    float* OUT = nhalf ? g_skip0 : g_h0;
#pragma unroll
    for (int mt = 0; mt < 2; mt++)
#pragma unroll
        for (int rr = 0; rr < 2; rr++) {
            int row = rowbase + mt * 16 + group + rr * 8;
            float ss = 0.f, sd = 0.f;
#pragma unroll
            for (int nt = 0; nt < 8; nt++) {
                float c0 = C[nt][mt][rr * 2], c1 = C[nt][mt][rr * 2 + 1];
                int col = nt * 8 + qk;
                if (row < n)
                    *(float2*)(OUT + (size_t)row * 64 + col) = make_float2(c0, c1);
                if (nhalf == 0) {
                    ss = fmaf(c0, __ldg(avs + col), fmaf(c1, __ldg(avs + col + 1), ss));
                    sd = fmaf(c0, __ldg(avd + col), fmaf(c1, __ldg(avd + col + 1), sd));
                }
            }
            if (nhalf == 0) {
                ss += __shfl_xor_sync(0xffffffffu, ss, 1);
                ss += __shfl_xor_sync(0xffffffffu, ss, 2);
                sd += __shfl_xor_sync(0xffffffffu, sd, 1);
                sd += __shfl_xor_sync(0xffffffffu, sd, 2);
                if ((lane & 3) == 0 && row < n) { g_ssrc0[row] = ss; g_sdst0[row] = sd; }
            }
        }
}

// ====== layer1 GEMM via mma.sync + fused scomp ============================
__global__ __launch_bounds__(128)
void gemm1_mma(const float* __restrict__ X,
               const float* __restrict__ avs, const float* __restrict__ avd, int n) {
    int tid = threadIdx.x, lane = tid & 31, mwarp = tid >> 5;
    int rowbase = blockIdx.x * 128 + mwarp * 32;
    int group = lane >> 2, qk = (lane & 3) * 2;

    float C[8][2][4];
#pragma unroll
    for (int a = 0; a < 8; a++)
#pragma unroll
        for (int b = 0; b < 2; b++)
#pragma unroll
            for (int c = 0; c < 4; c++) C[a][b][c] = 0.f;

#pragma unroll 1
    for (int ks = 0; ks < 4; ks++) {
        uint32_t ah[2][4], al[2][4];
#pragma unroll
        for (int mt = 0; mt < 2; mt++) {
            int r0 = rowbase + mt * 16 + group;
            int r1 = r0 + 8;
            int k0 = ks * 16 + qk;
            float2 z = make_float2(0.f, 0.f);
            float2 x00 = (r0 < n) ? *(const float2*)(X + (size_t)r0 * 64 + k0) : z;
            float2 x01 = (r0 < n) ? *(const float2*)(X + (size_t)r0 * 64 + k0 + 8) : z;
            float2 x10 = (r1 < n) ? *(const float2*)(X + (size_t)r1 * 64 + k0) : z;
            float2 x11 = (r1 < n) ? *(const float2*)(X + (size_t)r1 * 64 + k0 + 8) : z;
            ah[mt][0] = pack_hi(x00.x, x00.y); al[mt][0] = pack_lo(x00.x, x00.y);
            ah[mt][1] = pack_hi(x10.x, x10.y); al[mt][1] = pack_lo(x10.x, x10.y);
            ah[mt][2] = pack_hi(x01.x, x01.y); al[mt][2] = pack_lo(x01.x, x01.y);
            ah[mt][3] = pack_hi(x11.x, x11.y); al[mt][3] = pack_lo(x11.x, x11.y);
        }
        const uint4* bp = g_Bf1 + ((ks * 8) * 32 + lane);
#pragma unroll
        for (int nt = 0; nt < 8; nt++) {
            uint4 B = bp[nt * 32];
#pragma unroll
            for (int mt = 0; mt < 2; mt++) {
                mma16816(C[nt][mt], ah[mt], B.x, B.y);
                mma16816(C[nt][mt], al[mt], B.x, B.y);
                mma16816(C[nt][mt], ah[mt], B.z, B.w);
            }
        }
    }

#pragma unroll
    for (int mt = 0; mt < 2; mt++)
#pragma unroll
        for (int rr = 0; rr < 2; rr++) {
            int row = rowbase + mt * 16 + group + rr * 8;
            float ss = 0.f, sd = 0.f;
#pragma unroll
            for (int nt = 0; nt < 8; nt++) {
                float c0 = C[nt][mt][rr * 2], c1 = C[nt][mt][rr * 2 + 1];
                int col = nt * 8 + qk;
                if (row < n) {
                    if (nt < 4)
                        *(float2*)(g_h1p + (size_t)row * 32 + col) = make_float2(c0, c1);
                    else
                        *(float2*)(g_skip1 + (size_t)row * 32 + col - 32) = make_float2(c0, c1);
                }
                if (nt < 4) {
                    ss = fmaf(c0, __ldg(avs + col), fmaf(c1, __ldg(avs + col + 1), ss));
                    sd = fmaf(c0, __ldg(avd + col), fmaf(c1, __ldg(avd + col + 1), sd));
                }
            }
            ss += __shfl_xor_sync(0xffffffffu, ss, 1);
            ss += __shfl_xor_sync(0xffffffffu, ss, 2);
            sd += __shfl_xor_sync(0xffffffffu, sd, 1);
            sd += __shfl_xor_sync(0xffffffffu, sd, 2);
            if ((lane & 3) == 0 && row < n) { g_ssrc1[row] = ss; g_sdst1[row] = sd; }
        }
}

// ------- layer 0 aggregation: warp/node, register acc, fused finalize -----
__global__ __launch_bounds__(256)
void agg0_kernel(const float* __restrict__ b0,
                 const float* __restrict__ sb0, int n) {
    int gw   = (blockIdx.x * blockDim.x + threadIdx.x) >> 5;
    int lane = threadIdx.x & 31;
    if (gw >= n) return;
    const float2* h2 = reinterpret_cast<const float2*>(g_h0);

    float sd = g_sdst0[gw];
    float ws = __expf(leaky(g_ssrc0[gw] + sd));
    float2 hs = h2[gw * 32 + lane];
    float ax = ws * hs.x, ay = ws * hs.y;
    float dlane = 0.f;

    int start = g_off[gw], end = g_pos[gw];
    for (int base = start; base < end; base += 32) {
        int j = base + lane;
        int s = 0; float w = 0.f;
        if (j < end) {
            s = g_esrc[j];
            w = __expf(leaky(g_ssrc0[s] + sd));
        }
        dlane += w;
        int cnt = end - base; if (cnt > 32) cnt = 32;
        for (int k = 0; k < cnt; k++) {
            int   sk = __shfl_sync(0xffffffffu, s, k);
            float wk = __shfl_sync(0xffffffffu, w, k);
            float2 hv = h2[sk * 32 + lane];
            ax = fmaf(wk, hv.x, ax);
            ay = fmaf(wk, hv.y, ay);
        }
    }
#pragma unroll
    for (int off = 16; off; off >>= 1)
        dlane += __shfl_xor_sync(0xffffffffu, dlane, off);
    float inv = 1.f / (dlane + ws);

    float2 sk2 = reinterpret_cast<const float2*>(g_skip0)[gw * 32 + lane];
    float2 bb  = reinterpret_cast<const float2*>(b0)[lane];
    float2 sbv = reinterpret_cast<const float2*>(sb0)[lane];
    float v0 = fmaf(ax, inv, bb.x + sbv.x + sk2.x);
    float v1 = fmaf(ay, inv, bb.y + sbv.y + sk2.y);
    float2 o2;
    o2.x = v0 > 0.f ? v0 : expm1f(v0);
    o2.y = v1 > 0.f ? v1 : expm1f(v1);
    reinterpret_cast<float2*>(g_h1)[gw * 32 + lane] = o2;
}

// --- layer 1 aggregation: warp/node, fused finalize + log_softmax ---------
__global__ __launch_bounds__(256)
void agg1_kernel(const float* __restrict__ b1,
                 const float* __restrict__ sb1,
                 float* __restrict__ out, int n) {
    int gw   = (blockIdx.x * blockDim.x + threadIdx.x) >> 5;
    int lane = threadIdx.x & 31;
    if (gw >= n) return;

    float sd = g_sdst1[gw];
    float ws = __expf(leaky(g_ssrc1[gw] + sd));
    float hsl = g_h1p[gw * 32 + lane];
    float acc = ws * hsl;
    float dlane = 0.f;

    int start = g_off[gw], end = g_pos[gw];
    for (int base = start; base < end; base += 32) {
        int j = base + lane;
        int s = 0; float w = 0.f;
        if (j < end) {
            s = g_esrc[j];
            w = __expf(leaky(g_ssrc1[s] + sd));
        }
        dlane += w;
        int cnt = end - base; if (cnt > 32) cnt = 32;
        for (int k = 0; k < cnt; k++) {
            int   sk = __shfl_sync(0xffffffffu, s, k);
            float wk = __shfl_sync(0xffffffffu, w, k);
            acc = fmaf(wk, g_h1p[sk * 32 + lane], acc);
        }
    }
#pragma unroll
    for (int off = 16; off; off >>= 1)
        dlane += __shfl_xor_sync(0xffffffffu, dlane, off);
    float inv = 1.f / (dlane + ws);

    float z = fmaf(acc, inv, b1[lane] + sb1[lane] + g_skip1[gw * 32 + lane]);
    float m = z;
#pragma unroll
    for (int off = 16; off; off >>= 1)
        m = fmaxf(m, __shfl_xor_sync(0xffffffffu, m, off));
    float ex = __expf(z - m);
    float s = ex;
#pragma unroll
    for (int off = 16; off; off >>= 1)
        s += __shfl_xor_sync(0xffffffffu, s, off);
    out[gw * 32 + lane] = z - m - __logf(s);
}

// ---------- static stream/event resources (created before checkpoints) ----
struct SideStream {
    cudaStream_t s = nullptr;
    cudaEvent_t e_fork = nullptr, e_join = nullptr;
    bool ok = false;
    SideStream() {
        ok = (cudaStreamCreateWithFlags(&s, cudaStreamNonBlocking) == cudaSuccess) &&
             (cudaEventCreateWithFlags(&e_fork, cudaEventDisableTiming) == cudaSuccess) &&
             (cudaEventCreateWithFlags(&e_join, cudaEventDisableTiming) == cudaSuccess);
    }
};
static SideStream g_ss;

// ---------------- host ----------------
extern "C" void kernel_launch(void* const* d_in, const int* in_sizes, int n_in,
                              void* d_out, int out_size) {
    const float* x     = (const float*)d_in[0];
    const int*   ei    = (const int*)  d_in[1];
    const float* W0    = (const float*)d_in[2];
    const float* asrc0 = (const float*)d_in[3];
    const float* adst0 = (const float*)d_in[4];
    const float* b0    = (const float*)d_in[5];
    const float* sb0   = (const float*)d_in[7];
    const float* sW0   = (const float*)d_in[6];
    const float* W1    = (const float*)d_in[8];
    const float* asrc1 = (const float*)d_in[9];
    const float* adst1 = (const float*)d_in[10];
    const float* b1    = (const float*)d_in[11];
    const float* sW1   = (const float*)d_in[12];
    const float* sb1   = (const float*)d_in[13];
    float* out = (float*)d_out;

    const int n = in_sizes[0] / 128;   // 100000
    const int E = in_sizes[1] / 2;     // 1600000

    float* h1ptr;
    cudaGetSymbolAddress((void**)&h1ptr, g_h1);

    const int nodeBlocks = (n * 32 + 255) / 256;
    const int nb = (n + 1023) / 1024;
    const int gemmBlocks = (n + 127) / 128;

    cudaStream_t cs = g_ss.ok ? g_ss.s : (cudaStream_t)0;   // CSR chain stream

    // fork: CSR chain runs concurrently with prep_w + gemm0
    if (g_ss.ok) {
        cudaEventRecord(g_ss.e_fork, 0);
        cudaStreamWaitEvent(cs, g_ss.e_fork, 0);
    }

    // ---- CSR build on side stream ----
    hist_kernel<<<(E / 4 + 255) / 256, 256, 0, cs>>>(ei, E);
    scan1_kernel<<<nb, 1024, 0, cs>>>(n);
    scan2_kernel<<<1, 128, 0, cs>>>(nb);
    scan3_kernel<<<(n + 255) / 256, 256, 0, cs>>>(n);
    scatter_kernel<<<(E / 2 + 255) / 256, 256, 0, cs>>>(ei, E);

    // ---- main stream: weight prep + layer-0 GEMM (independent of CSR) ----
    prep_w<<<40, 256>>>(W0, sW0, W1, sW1);
    gemm0_mma<<<gemmBlocks, 256>>>(x, asrc0, adst0, n);

    // join: agg0 needs both CSR and gemm0 results
    if (g_ss.ok) {
        cudaEventRecord(g_ss.e_join, cs);
        cudaStreamWaitEvent(0, g_ss.e_join, 0);
    }

    agg0_kernel<<<nodeBlocks, 256>>>(b0, sb0, n);

    // ---- layer 1 ----
    gemm1_mma<<<gemmBlocks, 128>>>(h1ptr, asrc1, adst1, n);
    agg1_kernel<<<nodeBlocks, 256>>>(b1, sb1, out, n);
}